// round 15
// baseline (speedup 1.0000x reference)
#include <cuda_runtime.h>
#include <cuda_fp16.h>
#include <cstdint>

#define NJ 14
#define NB 2
#define NT 32768
#define NH 128
#define CIN 131

#define RS 68                 // AH row stride in u32 (272 B): ldmatrix/stmatrix conflict-free
#define BIAS_W 8704           // word offsets after AH[128][RS]
#define W0P_W  9088
#define W3_W   9472
#define SCR_W  9600
#define SMEM_BYTES 38912      // 9728 words

// fragment-ordered fp16x2 weights: [j][l][kc(8)][nfpg(8)][lane(32)][q(4)]
__device__ uint32_t g_w16[NJ * 3 * 8192];
// A-fragment-ordered fp16x2 c tiles: [b][tile][w(8)][kc(8)][lane(32)][q(4)]
__device__ uint32_t g_cf[NB * 256 * 8192];

// ---------- helpers ----------
__device__ __forceinline__ uint32_t smem_u32(const void* p) {
    uint32_t a;
    asm("{ .reg .u64 t; cvta.to.shared.u64 t, %1; cvt.u32.u64 %0, t; }" : "=r"(a) : "l"(p));
    return a;
}
__device__ __forceinline__ void ldsm4(uint32_t* r, uint32_t addr) {
    asm volatile("ldmatrix.sync.aligned.m8n8.x4.shared.b16 {%0,%1,%2,%3}, [%4];"
                 : "=r"(r[0]), "=r"(r[1]), "=r"(r[2]), "=r"(r[3]) : "r"(addr));
}
__device__ __forceinline__ void stsm4(uint32_t addr, uint32_t r0, uint32_t r1,
                                      uint32_t r2, uint32_t r3) {
    asm volatile("stmatrix.sync.aligned.m8n8.x4.shared.b16 [%0], {%1,%2,%3,%4};"
                 :: "r"(addr), "r"(r0), "r"(r1), "r"(r2), "r"(r3) : "memory");
}
__device__ __forceinline__ void mma16816(float* d, const uint32_t* a,
                                         uint32_t b0, uint32_t b1) {
    asm volatile(
        "mma.sync.aligned.m16n8k16.row.col.f32.f16.f16.f32 "
        "{%0,%1,%2,%3}, {%4,%5,%6,%7}, {%8,%9}, {%0,%1,%2,%3};"
        : "+f"(d[0]), "+f"(d[1]), "+f"(d[2]), "+f"(d[3])
        : "r"(a[0]), "r"(a[1]), "r"(a[2]), "r"(a[3]), "r"(b0), "r"(b1));
}
__device__ __forceinline__ uint32_t h2bits(half2 h) {
    return *reinterpret_cast<uint32_t*>(&h);
}

// ---------- fused pre-conversion ----------
// blocks 0..41: weights -> B-fragment order; blocks 42..553: c -> A-fragment order
__global__ void convert_all(const float* __restrict__ W0,
                            const float* __restrict__ W1,
                            const float* __restrict__ W2,
                            const float* __restrict__ c) {
    __shared__ uint32_t s[128 * 65];
    int bid = blockIdx.x;
    if (bid < 42) {
        int j = bid / 3, l = bid % 3;
        const float* W = (l == 0) ? W0 : ((l == 1) ? W1 : W2);
        int K = (l == 0) ? CIN : NH;
        int koff = (l == 0) ? 3 : 0;
        uint32_t* dst = g_w16 + (size_t)(j * 3 + l) * 8192;
        for (int i = threadIdx.x; i < 8192; i += blockDim.x) {
            int q = i & 3, lane = (i >> 2) & 31, nfpg = (i >> 7) & 7, kc = i >> 10;
            int n = nfpg * 16 + ((q >> 1) & 1) * 8 + (lane >> 2);
            int k = kc * 16 + (q & 1) * 8 + 2 * (lane & 3);
            const float* row = W + ((size_t)j * NH + n) * K + koff + k;
            dst[i] = h2bits(__floats2half2_rn(row[0], row[1]));
        }
    } else {
        int cid = bid - 42;
        int tile = cid & 255, b = cid >> 8;
        const float* cb = c + (size_t)b * NH * NT + tile * 128;
        uint32_t* dst = g_cf + ((size_t)b * 256 + tile) * 8192;
        for (int i = threadIdx.x; i < 8192; i += 256) {
            int t = i & 127, kw = i >> 7;
            float v0 = __ldg(cb + (size_t)(2 * kw) * NT + t);
            float v1 = __ldg(cb + (size_t)(2 * kw + 1) * NT + t);
            s[t * 65 + kw] = h2bits(__floats2half2_rn(v0, v1));
        }
        __syncthreads();
        // A-fragment order: i = ((w*8 + kc)*32 + lane)*4 + q
        for (int i = threadIdx.x; i < 8192; i += 256) {
            int q = i & 3, lane = (i >> 2) & 31, kc = (i >> 7) & 7, w = i >> 10;
            int t  = w * 16 + (lane >> 2) + ((q & 1) ? 8 : 0);
            int kw = kc * 8 + (lane & 3) + ((q >> 1) ? 4 : 0);
            dst[i] = s[t * 65 + kw];
        }
    }
}

// ---------- main kernel: 256 threads, warp tile 32(M)x64(N), 2 CTAs/SM ----------
__global__ __launch_bounds__(256, 2)
void ptf_hmma(const float* __restrict__ p,
              const float* __restrict__ ps,
              const float* __restrict__ b0g,
              const float* __restrict__ b1g,
              const float* __restrict__ b2g,
              const float* __restrict__ W0g,
              const float* __restrict__ W3g,
              const float* __restrict__ b3g,
              float* __restrict__ out) {
    extern __shared__ uint32_t sm[];
    float* bias_s = (float*)(sm + BIAS_W);   // [3][128]
    float* w0p_s  = (float*)(sm + W0P_W);    // [3][128]
    float* w3_s   = (float*)(sm + W3_W);     // [128]
    float* scr    = (float*)(sm + SCR_W);    // [128]

    const int tid = threadIdx.x, lane = tid & 31, wid = tid >> 5;
    const int mb = (wid & 3) * 32;        // t strip (32 rows)
    const int ni = wid >> 2;              // h strip id (64 cols)
    const int nb = ni * 64;
    const int t0 = blockIdx.x * 128, b = blockIdx.y, j = blockIdx.z;

    const uint32_t sbase = smem_u32(sm);
    const int arow_l = (lane & 7) + ((lane >> 3) & 1) * 8;
    const int akoff  = ((lane >> 4) & 1) * 16;

    uint32_t aoff[2];
#pragma unroll
    for (int mf = 0; mf < 2; mf++)
        aoff[mf] = sbase + (uint32_t)((mb + mf * 16 + arow_l) * (RS * 4) + akoff);

    // B-fragment gmem base (uint4): [(kc*8 + ni*4 + nfp)*32 + lane]
    const uint4* wf_base = (const uint4*)g_w16 + (size_t)(j * 3) * 2048 + (ni * 4) * 32 + lane;
    // layer-0 A fragments: [( (mb/16+mf)*8 + kc )*32 + lane]
    const uint4* ca = (const uint4*)g_cf + ((size_t)b * 256 + blockIdx.x) * 2048
                      + ((mb >> 4) * 8) * 32 + lane;

    // stmatrix base: per mf, matrix i = lane>>3 selects (t+8 | h+8) quadrant
    uint32_t stm_base[2];
#pragma unroll
    for (int mf = 0; mf < 2; mf++)
        stm_base[mf] = sbase + (uint32_t)((mb + mf * 16 + ((lane >> 3) & 1) * 8 + (lane & 7)) * (RS * 4)
                                          + nb * 2 + (lane >> 4) * 16);

    if (tid < 128) {
        bias_s[tid]       = __ldg(b0g + j * NH + tid);
        bias_s[128 + tid] = __ldg(b1g + j * NH + tid);
        bias_s[256 + tid] = __ldg(b2g + j * NH + tid);
        const float* w0r = W0g + ((size_t)j * NH + tid) * CIN;
        w0p_s[tid]       = __ldg(w0r);
        w0p_s[128 + tid] = __ldg(w0r + 1);
        w0p_s[256 + tid] = __ldg(w0r + 2);
        w3_s[tid] = __ldg(W3g + j * NH + tid);
        scr[tid] = 0.f;
    }
    __syncthreads();

    float acc3[4] = {0.f, 0.f, 0.f, 0.f};

    for (int l = 0; l < 3; l++) {
        const uint4* wf = wf_base + (size_t)l * 2048;

        float acc[2][8][4];
#pragma unroll
        for (int mf = 0; mf < 2; mf++)
#pragma unroll
            for (int nf = 0; nf < 8; nf++)
#pragma unroll
                for (int q = 0; q < 4; q++) acc[mf][nf][q] = 0.f;

        if (l == 0) {
            // A direct from gmem fragments (no smem staging)
#pragma unroll
            for (int kc = 0; kc < 8; kc++) {
                uint32_t a[2][4];
#pragma unroll
                for (int mf = 0; mf < 2; mf++) {
                    uint4 av = __ldg(ca + (mf * 8 + kc) * 32);
                    a[mf][0] = av.x; a[mf][1] = av.y; a[mf][2] = av.z; a[mf][3] = av.w;
                }
#pragma unroll
                for (int nfp = 0; nfp < 4; nfp++) {
                    uint4 bw = __ldg(wf + (kc * 8 + nfp) * 32);
#pragma unroll
                    for (int mf = 0; mf < 2; mf++) {
                        mma16816(acc[mf][2 * nfp],     a[mf], bw.x, bw.y);
                        mma16816(acc[mf][2 * nfp + 1], a[mf], bw.z, bw.w);
                    }
                }
            }
        } else {
#pragma unroll
            for (int kc = 0; kc < 8; kc++) {
                uint32_t a[2][4];
#pragma unroll
                for (int mf = 0; mf < 2; mf++)
                    ldsm4(a[mf], aoff[mf] + kc * 32);
#pragma unroll
                for (int nfp = 0; nfp < 4; nfp++) {
                    uint4 bw = __ldg(wf + (kc * 8 + nfp) * 32);
#pragma unroll
                    for (int mf = 0; mf < 2; mf++) {
                        mma16816(acc[mf][2 * nfp],     a[mf], bw.x, bw.y);
                        mma16816(acc[mf][2 * nfp + 1], a[mf], bw.z, bw.w);
                    }
                }
            }
        }

        if (l < 2) {
            // layer 0: AH not yet read by anyone -> no barrier before epilogue.
            // layer 1: AH reads of this layer done must be ensured before rewrite.
            if (l == 1) __syncthreads();

            float pva[2][3], pvb[2][3];
            if (l == 0) {
#pragma unroll
                for (int mf = 0; mf < 2; mf++) {
                    int r0 = t0 + mb + mf * 16 + (lane >> 2);
#pragma unroll
                    for (int d = 0; d < 3; d++) {
                        const float* pp = p + ((size_t)b * NJ * 3 + j * 3 + d) * NT;
                        pva[mf][d] = __ldg(pp + r0);
                        pvb[mf][d] = __ldg(pp + r0 + 8);
                    }
                }
            }
            // epilogue: nf-pair outer, mf inner; bias/w0p loaded once per nf
            const float* bl = bias_s + l * 128;
#pragma unroll
            for (int np = 0; np < 4; np++) {
                uint32_t rr[2][4];
#pragma unroll
                for (int half = 0; half < 2; half++) {
                    const int nf = 2 * np + half;
                    const int h = nb + nf * 8 + 2 * (lane & 3);
                    const float2 bb = *(const float2*)(bl + h);
                    float2 w0, w1, w2;
                    if (l == 0) {
                        w0 = *(const float2*)(w0p_s + h);
                        w1 = *(const float2*)(w0p_s + 128 + h);
                        w2 = *(const float2*)(w0p_s + 256 + h);
                    }
#pragma unroll
                    for (int mf = 0; mf < 2; mf++) {
                        float v0 = acc[mf][nf][0] + bb.x;
                        float v1 = acc[mf][nf][1] + bb.y;
                        float v2 = acc[mf][nf][2] + bb.x;
                        float v3 = acc[mf][nf][3] + bb.y;
                        if (l == 0) {
                            v0 = fmaf(pva[mf][0], w0.x, v0); v1 = fmaf(pva[mf][0], w0.y, v1);
                            v2 = fmaf(pvb[mf][0], w0.x, v2); v3 = fmaf(pvb[mf][0], w0.y, v3);
                            v0 = fmaf(pva[mf][1], w1.x, v0); v1 = fmaf(pva[mf][1], w1.y, v1);
                            v2 = fmaf(pvb[mf][1], w1.x, v2); v3 = fmaf(pvb[mf][1], w1.y, v3);
                            v0 = fmaf(pva[mf][2], w2.x, v0); v1 = fmaf(pva[mf][2], w2.y, v1);
                            v2 = fmaf(pvb[mf][2], w2.x, v2); v3 = fmaf(pvb[mf][2], w2.y, v3);
                        }
                        v0 = fmaxf(v0, 0.f); v1 = fmaxf(v1, 0.f);
                        v2 = fmaxf(v2, 0.f); v3 = fmaxf(v3, 0.f);
                        rr[mf][2 * half]     = h2bits(__floats2half2_rn(v0, v1));
                        rr[mf][2 * half + 1] = h2bits(__floats2half2_rn(v2, v3));
                    }
                }
#pragma unroll
                for (int mf = 0; mf < 2; mf++)
                    stsm4(stm_base[mf] + np * 32, rr[mf][0], rr[mf][1], rr[mf][2], rr[mf][3]);
            }
            __syncthreads();   // A' visible before next layer's ldsm
        } else {
            // fused head: regs + read-only smem, no barrier needed
#pragma unroll
            for (int nf = 0; nf < 8; nf++) {
                const int h = nb + nf * 8 + 2 * (lane & 3);
                const float2 bb = *(const float2*)(bias_s + 256 + h);
                const float2 w3v = *(const float2*)(w3_s + h);
#pragma unroll
                for (int mf = 0; mf < 2; mf++) {
                    float v0 = fmaxf(acc[mf][nf][0] + bb.x, 0.f);
                    float v1 = fmaxf(acc[mf][nf][1] + bb.y, 0.f);
                    float v2 = fmaxf(acc[mf][nf][2] + bb.x, 0.f);
                    float v3 = fmaxf(acc[mf][nf][3] + bb.y, 0.f);
                    acc3[0 + 2 * mf] += v0 * w3v.x + v1 * w3v.y;
                    acc3[1 + 2 * mf] += v2 * w3v.x + v3 * w3v.y;
                }
            }
        }
    }

    // head reduce: quad shuffle, then atomics into scr (2 h-warps per t-row)
#pragma unroll
    for (int s = 0; s < 4; s++) {
        acc3[s] += __shfl_xor_sync(0xffffffffu, acc3[s], 1);
        acc3[s] += __shfl_xor_sync(0xffffffffu, acc3[s], 2);
    }
    if ((lane & 3) == 0) {
#pragma unroll
        for (int s = 0; s < 4; s++) {
            int r = mb + (s >> 1) * 16 + (lane >> 2) + (s & 1) * 8;
            atomicAdd(scr + r, acc3[s]);
        }
    }
    __syncthreads();

    if (tid < 128) {
        float o = scr[tid] + __ldg(b3g + j);
        float w = __ldg(ps + ((size_t)b * NJ + j) * NT + t0 + tid);
        atomicAdd(out + (size_t)b * NT + t0 + tid, o * w * (1.0f / 14.0f));
    }
}

extern "C" void kernel_launch(void* const* d_in, const int* in_sizes, int n_in,
                              void* d_out, int out_size) {
    (void)in_sizes; (void)n_in;
    const float* p  = (const float*)d_in[0];
    // d_in[1] = z (unused by the reference)
    const float* c  = (const float*)d_in[2];
    const float* ps = (const float*)d_in[3];
    const float* W0 = (const float*)d_in[4];
    const float* b0 = (const float*)d_in[5];
    const float* W1 = (const float*)d_in[6];
    const float* b1 = (const float*)d_in[7];
    const float* W2 = (const float*)d_in[8];
    const float* b2 = (const float*)d_in[9];
    const float* W3 = (const float*)d_in[10];
    const float* b3 = (const float*)d_in[11];
    float* out = (float*)d_out;

    cudaMemsetAsync(out, 0, (size_t)out_size * sizeof(float));

    convert_all<<<554, 256>>>(W0, W1, W2, c);

    cudaFuncSetAttribute(ptf_hmma, cudaFuncAttributeMaxDynamicSharedMemorySize,
                         SMEM_BYTES);
    dim3 grid(NT / 128, NB, NJ);   // 256 x 2 x 14 = 7168 CTAs, j slowest
    ptf_hmma<<<grid, 256, SMEM_BYTES>>>(p, ps, b0, b1, b2, W0, W3, b3, out);
}

// round 16
// speedup vs baseline: 1.2049x; 1.2049x over previous
#include <cuda_runtime.h>
#include <cuda_fp16.h>
#include <cstdint>

#define NJ 14
#define NB 2
#define NT 32768
#define NH 128
#define CIN 131

#define RS 68                 // AH row stride in u32 (272 B): ldmatrix/stmatrix conflict-free
// word offsets after AH[64][RS] = 4352 words
#define BIAS_W 4352
#define W0P_W  4736
#define W3_W   5120
#define SCR_W  5248
#define SMEM_BYTES 21248      // 5312 words; x4 CTAs = 85 KB

// fragment-ordered fp16x2 weights: [j][l][kc(8)][nfpg(8)][lane(32)][q(4)]
__device__ uint32_t g_w16[NJ * 3 * 8192];
// fp16x2 c tiles, t-major: [b][tile128][t(128)][kw(64)]
__device__ uint32_t g_c16[NB * 256 * 8192];

// ---------- helpers ----------
__device__ __forceinline__ uint32_t smem_u32(const void* p) {
    uint32_t a;
    asm("{ .reg .u64 t; cvta.to.shared.u64 t, %1; cvt.u32.u64 %0, t; }" : "=r"(a) : "l"(p));
    return a;
}
__device__ __forceinline__ void ldsm4(uint32_t* r, uint32_t addr) {
    asm volatile("ldmatrix.sync.aligned.m8n8.x4.shared.b16 {%0,%1,%2,%3}, [%4];"
                 : "=r"(r[0]), "=r"(r[1]), "=r"(r[2]), "=r"(r[3]) : "r"(addr));
}
__device__ __forceinline__ void stsm4(uint32_t addr, uint32_t r0, uint32_t r1,
                                      uint32_t r2, uint32_t r3) {
    asm volatile("stmatrix.sync.aligned.m8n8.x4.shared.b16 [%0], {%1,%2,%3,%4};"
                 :: "r"(addr), "r"(r0), "r"(r1), "r"(r2), "r"(r3) : "memory");
}
__device__ __forceinline__ void mma16816(float* d, const uint32_t* a,
                                         uint32_t b0, uint32_t b1) {
    asm volatile(
        "mma.sync.aligned.m16n8k16.row.col.f32.f16.f16.f32 "
        "{%0,%1,%2,%3}, {%4,%5,%6,%7}, {%8,%9}, {%0,%1,%2,%3};"
        : "+f"(d[0]), "+f"(d[1]), "+f"(d[2]), "+f"(d[3])
        : "r"(a[0]), "r"(a[1]), "r"(a[2]), "r"(a[3]), "r"(b0), "r"(b1));
}
__device__ __forceinline__ void cpasync16(uint32_t dst, const void* src) {
    asm volatile("cp.async.cg.shared.global [%0], [%1], 16;" :: "r"(dst), "l"(src));
}
#define CP_COMMIT() asm volatile("cp.async.commit_group;" ::: "memory")
#define CP_WAIT0()  asm volatile("cp.async.wait_group 0;" ::: "memory")

__device__ __forceinline__ uint32_t h2bits(half2 h) {
    return *reinterpret_cast<uint32_t*>(&h);
}

// ---------- fused pre-conversion: W fragments (blocks 0..41) + c tiles (42..553) ----------
__global__ void convert_all(const float* __restrict__ W0,
                            const float* __restrict__ W1,
                            const float* __restrict__ W2,
                            const float* __restrict__ c) {
    __shared__ uint32_t s[128 * 65];
    int bid = blockIdx.x;
    if (bid < 42) {
        int j = bid / 3, l = bid % 3;
        const float* W = (l == 0) ? W0 : ((l == 1) ? W1 : W2);
        int K = (l == 0) ? CIN : NH;
        int koff = (l == 0) ? 3 : 0;
        uint32_t* dst = g_w16 + (size_t)(j * 3 + l) * 8192;
        for (int i = threadIdx.x; i < 8192; i += blockDim.x) {
            int q = i & 3, lane = (i >> 2) & 31, nfpg = (i >> 7) & 7, kc = i >> 10;
            int n = nfpg * 16 + ((q >> 1) & 1) * 8 + (lane >> 2);
            int k = kc * 16 + (q & 1) * 8 + 2 * (lane & 3);
            const float* row = W + ((size_t)j * NH + n) * K + koff + k;
            dst[i] = h2bits(__floats2half2_rn(row[0], row[1]));
        }
    } else {
        int cid = bid - 42;
        int tile = cid & 255, b = cid >> 8;
        const float* cb = c + (size_t)b * NH * NT + tile * 128;
        uint32_t* dst = g_c16 + ((size_t)b * 256 + tile) * 8192;
        for (int i = threadIdx.x; i < 8192; i += 256) {
            int t = i & 127, kw = i >> 7;
            float v0 = __ldg(cb + (size_t)(2 * kw) * NT + t);
            float v1 = __ldg(cb + (size_t)(2 * kw + 1) * NT + t);
            s[t * 65 + kw] = h2bits(__floats2half2_rn(v0, v1));
        }
        __syncthreads();
        for (int i = threadIdx.x; i < 8192; i += 256)
            dst[i] = s[(i >> 6) * 65 + (i & 63)];
    }
}

// ---------- main kernel: 128 threads (4 warps), tile 64t x 128h, 4 CTAs/SM ----------
__global__ __launch_bounds__(128, 4)
void ptf_hmma(const float* __restrict__ p,
              const float* __restrict__ ps,
              const float* __restrict__ b0g,
              const float* __restrict__ b1g,
              const float* __restrict__ b2g,
              const float* __restrict__ W0g,
              const float* __restrict__ W3g,
              const float* __restrict__ b3g,
              float* __restrict__ out) {
    extern __shared__ uint32_t sm[];
    float* bias_s = (float*)(sm + BIAS_W);   // [3][128]
    float* w0p_s  = (float*)(sm + W0P_W);    // [3][128]
    float* w3_s   = (float*)(sm + W3_W);     // [128]
    float* scr    = (float*)(sm + SCR_W);    // [64]

    const int tid = threadIdx.x, lane = tid & 31, wid = tid >> 5;
    const int mb = (wid & 1) * 32;        // t strip (32 rows of the 64-row tile)
    const int ni = wid >> 1;              // h strip id (64 cols)
    const int nb = ni * 64;
    const int t0 = blockIdx.x * 64, b = blockIdx.y, j = blockIdx.z;

    const uint32_t sbase = smem_u32(sm);
    const int arow_l = (lane & 7) + ((lane >> 3) & 1) * 8;
    const int akoff  = ((lane >> 4) & 1) * 16;

    uint32_t aoff[2];
#pragma unroll
    for (int mf = 0; mf < 2; mf++)
        aoff[mf] = sbase + (uint32_t)((mb + mf * 16 + arow_l) * (RS * 4) + akoff);

    // B-fragment gmem base (uint4): [(kc*8 + ni*4 + nfp)*32 + lane]
    const uint4* wf_base = (const uint4*)g_w16 + (size_t)(j * 3) * 2048 + (ni * 4) * 32 + lane;

    // stmatrix base: per mf, matrix i = lane>>3 selects (t+8 | h+8) quadrant
    uint32_t stm_base[2];
#pragma unroll
    for (int mf = 0; mf < 2; mf++)
        stm_base[mf] = sbase + (uint32_t)((mb + mf * 16 + ((lane >> 3) & 1) * 8 + (lane & 7)) * (RS * 4)
                                          + nb * 2 + (lane >> 4) * 16);

    // ---- stage this CTA's 64 c rows (pre-converted) via cp.async ----
    {
        const uint4* csrc = (const uint4*)g_c16
            + ((size_t)b * 256 + (blockIdx.x >> 1)) * 2048
            + (size_t)(blockIdx.x & 1) * 1024;     // 64 rows x 16 uint4
        for (int i = tid; i < 1024; i += 128)
            cpasync16(sbase + (i >> 4) * (RS * 4) + (i & 15) * 16, csrc + i);
        CP_COMMIT();
    }
    {
        bias_s[tid]       = __ldg(b0g + j * NH + tid);
        bias_s[128 + tid] = __ldg(b1g + j * NH + tid);
        bias_s[256 + tid] = __ldg(b2g + j * NH + tid);
        const float* w0r = W0g + ((size_t)j * NH + tid) * CIN;
        w0p_s[tid]       = __ldg(w0r);
        w0p_s[128 + tid] = __ldg(w0r + 1);
        w0p_s[256 + tid] = __ldg(w0r + 2);
        w3_s[tid] = __ldg(W3g + j * NH + tid);
        if (tid < 64) scr[tid] = 0.f;
    }
    CP_WAIT0();
    __syncthreads();

    float acc3[4] = {0.f, 0.f, 0.f, 0.f};

    for (int l = 0; l < 3; l++) {
        const uint4* wf = wf_base + (size_t)l * 2048;

        float acc[2][8][4];
#pragma unroll
        for (int mf = 0; mf < 2; mf++)
#pragma unroll
            for (int nf = 0; nf < 8; nf++)
#pragma unroll
                for (int q = 0; q < 4; q++) acc[mf][nf][q] = 0.f;

#pragma unroll
        for (int kc = 0; kc < 8; kc++) {
            uint32_t a[2][4];
#pragma unroll
            for (int mf = 0; mf < 2; mf++)
                ldsm4(a[mf], aoff[mf] + kc * 32);
#pragma unroll
            for (int nfp = 0; nfp < 4; nfp++) {
                uint4 bw = __ldg(wf + (kc * 8 + nfp) * 32);
#pragma unroll
                for (int mf = 0; mf < 2; mf++) {
                    mma16816(acc[mf][2 * nfp],     a[mf], bw.x, bw.y);
                    mma16816(acc[mf][2 * nfp + 1], a[mf], bw.z, bw.w);
                }
            }
        }

        if (l < 2) {
            __syncthreads();   // all AH reads of this layer done (before in-place rewrite)

            float pva[2][3], pvb[2][3];
            if (l == 0) {
#pragma unroll
                for (int mf = 0; mf < 2; mf++) {
                    int r0 = t0 + mb + mf * 16 + (lane >> 2);
#pragma unroll
                    for (int d = 0; d < 3; d++) {
                        const float* pp = p + ((size_t)b * NJ * 3 + j * 3 + d) * NT;
                        pva[mf][d] = __ldg(pp + r0);
                        pvb[mf][d] = __ldg(pp + r0 + 8);
                    }
                }
            }
            // epilogue: nf-pair outer, mf inner; bias/w0p loaded once per nf
            const float* bl = bias_s + l * 128;
#pragma unroll
            for (int np = 0; np < 4; np++) {
                uint32_t rr[2][4];
#pragma unroll
                for (int half = 0; half < 2; half++) {
                    const int nf = 2 * np + half;
                    const int h = nb + nf * 8 + 2 * (lane & 3);
                    const float2 bb = *(const float2*)(bl + h);
                    float2 w0, w1, w2;
                    if (l == 0) {
                        w0 = *(const float2*)(w0p_s + h);
                        w1 = *(const float2*)(w0p_s + 128 + h);
                        w2 = *(const float2*)(w0p_s + 256 + h);
                    }
#pragma unroll
                    for (int mf = 0; mf < 2; mf++) {
                        float v0 = acc[mf][nf][0] + bb.x;
                        float v1 = acc[mf][nf][1] + bb.y;
                        float v2 = acc[mf][nf][2] + bb.x;
                        float v3 = acc[mf][nf][3] + bb.y;
                        if (l == 0) {
                            v0 = fmaf(pva[mf][0], w0.x, v0); v1 = fmaf(pva[mf][0], w0.y, v1);
                            v2 = fmaf(pvb[mf][0], w0.x, v2); v3 = fmaf(pvb[mf][0], w0.y, v3);
                            v0 = fmaf(pva[mf][1], w1.x, v0); v1 = fmaf(pva[mf][1], w1.y, v1);
                            v2 = fmaf(pvb[mf][1], w1.x, v2); v3 = fmaf(pvb[mf][1], w1.y, v3);
                            v0 = fmaf(pva[mf][2], w2.x, v0); v1 = fmaf(pva[mf][2], w2.y, v1);
                            v2 = fmaf(pvb[mf][2], w2.x, v2); v3 = fmaf(pvb[mf][2], w2.y, v3);
                        }
                        v0 = fmaxf(v0, 0.f); v1 = fmaxf(v1, 0.f);
                        v2 = fmaxf(v2, 0.f); v3 = fmaxf(v3, 0.f);
                        rr[mf][2 * half]     = h2bits(__floats2half2_rn(v0, v1));
                        rr[mf][2 * half + 1] = h2bits(__floats2half2_rn(v2, v3));
                    }
                }
#pragma unroll
                for (int mf = 0; mf < 2; mf++)
                    stsm4(stm_base[mf] + np * 32, rr[mf][0], rr[mf][1], rr[mf][2], rr[mf][3]);
            }
            __syncthreads();   // A' visible before next layer's ldsm
        } else {
            // fused head: regs + read-only smem, no barrier needed
#pragma unroll
            for (int nf = 0; nf < 8; nf++) {
                const int h = nb + nf * 8 + 2 * (lane & 3);
                const float2 bb = *(const float2*)(bias_s + 256 + h);
                const float2 w3v = *(const float2*)(w3_s + h);
#pragma unroll
                for (int mf = 0; mf < 2; mf++) {
                    float v0 = fmaxf(acc[mf][nf][0] + bb.x, 0.f);
                    float v1 = fmaxf(acc[mf][nf][1] + bb.y, 0.f);
                    float v2 = fmaxf(acc[mf][nf][2] + bb.x, 0.f);
                    float v3 = fmaxf(acc[mf][nf][3] + bb.y, 0.f);
                    acc3[0 + 2 * mf] += v0 * w3v.x + v1 * w3v.y;
                    acc3[1 + 2 * mf] += v2 * w3v.x + v3 * w3v.y;
                }
            }
        }
    }

    // head reduce: quad shuffle, then atomics into scr (2 h-warps per t-row)
#pragma unroll
    for (int s = 0; s < 4; s++) {
        acc3[s] += __shfl_xor_sync(0xffffffffu, acc3[s], 1);
        acc3[s] += __shfl_xor_sync(0xffffffffu, acc3[s], 2);
    }
    if ((lane & 3) == 0) {
#pragma unroll
        for (int s = 0; s < 4; s++) {
            int r = mb + (s >> 1) * 16 + (lane >> 2) + (s & 1) * 8;
            atomicAdd(scr + r, acc3[s]);
        }
    }
    __syncthreads();

    if (tid < 64) {
        float o = scr[tid] + __ldg(b3g + j);
        float w = __ldg(ps + ((size_t)b * NJ + j) * NT + t0 + tid);
        atomicAdd(out + (size_t)b * NT + t0 + tid, o * w * (1.0f / 14.0f));
    }
}

extern "C" void kernel_launch(void* const* d_in, const int* in_sizes, int n_in,
                              void* d_out, int out_size) {
    (void)in_sizes; (void)n_in;
    const float* p  = (const float*)d_in[0];
    // d_in[1] = z (unused by the reference)
    const float* c  = (const float*)d_in[2];
    const float* ps = (const float*)d_in[3];
    const float* W0 = (const float*)d_in[4];
    const float* b0 = (const float*)d_in[5];
    const float* W1 = (const float*)d_in[6];
    const float* b1 = (const float*)d_in[7];
    const float* W2 = (const float*)d_in[8];
    const float* b2 = (const float*)d_in[9];
    const float* W3 = (const float*)d_in[10];
    const float* b3 = (const float*)d_in[11];
    float* out = (float*)d_out;

    cudaMemsetAsync(out, 0, (size_t)out_size * sizeof(float));

    convert_all<<<554, 256>>>(W0, W1, W2, c);

    cudaFuncSetAttribute(ptf_hmma, cudaFuncAttributeMaxDynamicSharedMemorySize,
                         SMEM_BYTES);
    dim3 grid(NT / 64, NB, NJ);   // 512 x 2 x 14 = 14336 CTAs, j slowest
    ptf_hmma<<<grid, 128, SMEM_BYTES>>>(p, ps, b0, b1, b2, W0, W3, b3, out);
}

// round 17
// speedup vs baseline: 1.2411x; 1.0301x over previous
#include <cuda_runtime.h>
#include <cuda_fp16.h>
#include <cstdint>

#define NJ 14
#define NB 2
#define NT 32768
#define NH 128
#define CIN 131

#define RS 68                 // AH row stride in u32 (272 B): ldmatrix/stmatrix conflict-free
// word offsets after AH[32][RS] = 2176 words
#define BIAS_W 2176
#define W0P_W  2560
#define W3_W   2944
#define SMEM_BYTES 12288      // 3072 words; x8 CTAs = 96 KB

// fragment-ordered fp16x2 weights: [j][l][kc(8)][nfpg(8)][lane(32)][q(4)]
__device__ uint32_t g_w16[NJ * 3 * 8192];
// fp16x2 c tiles, t-major: [b][tile128][t(128)][kw(64)]
__device__ uint32_t g_c16[NB * 256 * 8192];

// ---------- helpers ----------
__device__ __forceinline__ uint32_t smem_u32(const void* p) {
    uint32_t a;
    asm("{ .reg .u64 t; cvta.to.shared.u64 t, %1; cvt.u32.u64 %0, t; }" : "=r"(a) : "l"(p));
    return a;
}
__device__ __forceinline__ void ldsm4(uint32_t* r, uint32_t addr) {
    asm volatile("ldmatrix.sync.aligned.m8n8.x4.shared.b16 {%0,%1,%2,%3}, [%4];"
                 : "=r"(r[0]), "=r"(r[1]), "=r"(r[2]), "=r"(r[3]) : "r"(addr));
}
__device__ __forceinline__ void stsm4(uint32_t addr, uint32_t r0, uint32_t r1,
                                      uint32_t r2, uint32_t r3) {
    asm volatile("stmatrix.sync.aligned.m8n8.x4.shared.b16 [%0], {%1,%2,%3,%4};"
                 :: "r"(addr), "r"(r0), "r"(r1), "r"(r2), "r"(r3) : "memory");
}
__device__ __forceinline__ void mma16816(float* d, const uint32_t* a,
                                         uint32_t b0, uint32_t b1) {
    asm volatile(
        "mma.sync.aligned.m16n8k16.row.col.f32.f16.f16.f32 "
        "{%0,%1,%2,%3}, {%4,%5,%6,%7}, {%8,%9}, {%0,%1,%2,%3};"
        : "+f"(d[0]), "+f"(d[1]), "+f"(d[2]), "+f"(d[3])
        : "r"(a[0]), "r"(a[1]), "r"(a[2]), "r"(a[3]), "r"(b0), "r"(b1));
}
__device__ __forceinline__ void cpasync16(uint32_t dst, const void* src) {
    asm volatile("cp.async.cg.shared.global [%0], [%1], 16;" :: "r"(dst), "l"(src));
}
#define CP_COMMIT() asm volatile("cp.async.commit_group;" ::: "memory")
#define CP_WAIT0()  asm volatile("cp.async.wait_group 0;" ::: "memory")

__device__ __forceinline__ uint32_t h2bits(half2 h) {
    return *reinterpret_cast<uint32_t*>(&h);
}

// ---------- fused pre-conversion: W fragments (blocks 0..41) + c tiles (42..553) ----------
__global__ void convert_all(const float* __restrict__ W0,
                            const float* __restrict__ W1,
                            const float* __restrict__ W2,
                            const float* __restrict__ c) {
    __shared__ uint32_t s[128 * 65];
    int bid = blockIdx.x;
    if (bid < 42) {
        int j = bid / 3, l = bid % 3;
        const float* W = (l == 0) ? W0 : ((l == 1) ? W1 : W2);
        int K = (l == 0) ? CIN : NH;
        int koff = (l == 0) ? 3 : 0;
        uint32_t* dst = g_w16 + (size_t)(j * 3 + l) * 8192;
        for (int i = threadIdx.x; i < 8192; i += blockDim.x) {
            int q = i & 3, lane = (i >> 2) & 31, nfpg = (i >> 7) & 7, kc = i >> 10;
            int n = nfpg * 16 + ((q >> 1) & 1) * 8 + (lane >> 2);
            int k = kc * 16 + (q & 1) * 8 + 2 * (lane & 3);
            const float* row = W + ((size_t)j * NH + n) * K + koff + k;
            dst[i] = h2bits(__floats2half2_rn(row[0], row[1]));
        }
    } else {
        int cid = bid - 42;
        int tile = cid & 255, b = cid >> 8;
        const float* cb = c + (size_t)b * NH * NT + tile * 128;
        uint32_t* dst = g_c16 + ((size_t)b * 256 + tile) * 8192;
        for (int i = threadIdx.x; i < 8192; i += 256) {
            int t = i & 127, kw = i >> 7;
            float v0 = __ldg(cb + (size_t)(2 * kw) * NT + t);
            float v1 = __ldg(cb + (size_t)(2 * kw + 1) * NT + t);
            s[t * 65 + kw] = h2bits(__floats2half2_rn(v0, v1));
        }
        __syncthreads();
        for (int i = threadIdx.x; i < 8192; i += 256)
            dst[i] = s[(i >> 6) * 65 + (i & 63)];
    }
}

// ---------- main kernel: 64 threads (2 warps), tile 32t x 128h, 8 CTAs/SM ----------
__global__ __launch_bounds__(64, 8)
void ptf_hmma(const float* __restrict__ p,
              const float* __restrict__ ps,
              const float* __restrict__ b0g,
              const float* __restrict__ b1g,
              const float* __restrict__ b2g,
              const float* __restrict__ W0g,
              const float* __restrict__ W3g,
              const float* __restrict__ b3g,
              float* __restrict__ out) {
    extern __shared__ uint32_t sm[];
    float* bias_s = (float*)(sm + BIAS_W);   // [3][128]
    float* w0p_s  = (float*)(sm + W0P_W);    // [3][128]
    float* w3_s   = (float*)(sm + W3_W);     // [128]

    const int tid = threadIdx.x, lane = tid & 31, wid = tid >> 5;
    const int ni = wid;                   // h strip id (64 cols)
    const int nb = ni * 64;
    const int t0 = blockIdx.x * 32, b = blockIdx.y, j = blockIdx.z;

    const uint32_t sbase = smem_u32(sm);
    const int arow_l = (lane & 7) + ((lane >> 3) & 1) * 8;
    const int akoff  = ((lane >> 4) & 1) * 16;

    uint32_t aoff[2];
#pragma unroll
    for (int mf = 0; mf < 2; mf++)
        aoff[mf] = sbase + (uint32_t)((mf * 16 + arow_l) * (RS * 4) + akoff);

    // B-fragment gmem base (uint4): [(kc*8 + ni*4 + nfp)*32 + lane]
    const uint4* wf_base = (const uint4*)g_w16 + (size_t)(j * 3) * 2048 + (ni * 4) * 32 + lane;

    // stmatrix base: per mf, matrix i = lane>>3 selects (t+8 | h+8) quadrant
    uint32_t stm_base[2];
#pragma unroll
    for (int mf = 0; mf < 2; mf++)
        stm_base[mf] = sbase + (uint32_t)((mf * 16 + ((lane >> 3) & 1) * 8 + (lane & 7)) * (RS * 4)
                                          + nb * 2 + (lane >> 4) * 16);

    // ---- stage this CTA's 32 c rows (pre-converted) via cp.async ----
    {
        const uint4* csrc = (const uint4*)g_c16
            + ((size_t)b * 256 + (blockIdx.x >> 2)) * 2048
            + (size_t)(blockIdx.x & 3) * 512;      // 32 rows x 16 uint4
        for (int i = tid; i < 512; i += 64)
            cpasync16(sbase + (i >> 4) * (RS * 4) + (i & 15) * 16, csrc + i);
        CP_COMMIT();
    }
#pragma unroll
    for (int i = tid; i < 128; i += 64) {
        bias_s[i]       = __ldg(b0g + j * NH + i);
        bias_s[128 + i] = __ldg(b1g + j * NH + i);
        bias_s[256 + i] = __ldg(b2g + j * NH + i);
        const float* w0r = W0g + ((size_t)j * NH + i) * CIN;
        w0p_s[i]       = __ldg(w0r);
        w0p_s[128 + i] = __ldg(w0r + 1);
        w0p_s[256 + i] = __ldg(w0r + 2);
        w3_s[i] = __ldg(W3g + j * NH + i);
    }
    CP_WAIT0();
    __syncthreads();

    for (int l = 0; l < 3; l++) {
        const uint4* wf = wf_base + (size_t)l * 2048;

        float acc[2][8][4];
#pragma unroll
        for (int mf = 0; mf < 2; mf++)
#pragma unroll
            for (int nf = 0; nf < 8; nf++)
#pragma unroll
                for (int q = 0; q < 4; q++) acc[mf][nf][q] = 0.f;

#pragma unroll
        for (int kc = 0; kc < 8; kc++) {
            uint32_t a[2][4];
#pragma unroll
            for (int mf = 0; mf < 2; mf++)
                ldsm4(a[mf], aoff[mf] + kc * 32);
#pragma unroll
            for (int nfp = 0; nfp < 4; nfp++) {
                uint4 bw = __ldg(wf + (kc * 8 + nfp) * 32);
#pragma unroll
                for (int mf = 0; mf < 2; mf++) {
                    mma16816(acc[mf][2 * nfp],     a[mf], bw.x, bw.y);
                    mma16816(acc[mf][2 * nfp + 1], a[mf], bw.z, bw.w);
                }
            }
        }

        if (l < 2) {
            __syncthreads();   // both warps done reading AH (before in-place rewrite)

            float pva[2][3], pvb[2][3];
            if (l == 0) {
#pragma unroll
                for (int mf = 0; mf < 2; mf++) {
                    int r0 = t0 + mf * 16 + (lane >> 2);
#pragma unroll
                    for (int d = 0; d < 3; d++) {
                        const float* pp = p + ((size_t)b * NJ * 3 + j * 3 + d) * NT;
                        pva[mf][d] = __ldg(pp + r0);
                        pvb[mf][d] = __ldg(pp + r0 + 8);
                    }
                }
            }
            // epilogue: nf-pair outer, mf inner; bias/w0p loaded once per nf
            const float* bl = bias_s + l * 128;
#pragma unroll
            for (int np = 0; np < 4; np++) {
                uint32_t rr[2][4];
#pragma unroll
                for (int half = 0; half < 2; half++) {
                    const int nf = 2 * np + half;
                    const int h = nb + nf * 8 + 2 * (lane & 3);
                    const float2 bb = *(const float2*)(bl + h);
                    float2 w0, w1, w2;
                    if (l == 0) {
                        w0 = *(const float2*)(w0p_s + h);
                        w1 = *(const float2*)(w0p_s + 128 + h);
                        w2 = *(const float2*)(w0p_s + 256 + h);
                    }
#pragma unroll
                    for (int mf = 0; mf < 2; mf++) {
                        float v0 = acc[mf][nf][0] + bb.x;
                        float v1 = acc[mf][nf][1] + bb.y;
                        float v2 = acc[mf][nf][2] + bb.x;
                        float v3 = acc[mf][nf][3] + bb.y;
                        if (l == 0) {
                            v0 = fmaf(pva[mf][0], w0.x, v0); v1 = fmaf(pva[mf][0], w0.y, v1);
                            v2 = fmaf(pvb[mf][0], w0.x, v2); v3 = fmaf(pvb[mf][0], w0.y, v3);
                            v0 = fmaf(pva[mf][1], w1.x, v0); v1 = fmaf(pva[mf][1], w1.y, v1);
                            v2 = fmaf(pvb[mf][1], w1.x, v2); v3 = fmaf(pvb[mf][1], w1.y, v3);
                            v0 = fmaf(pva[mf][2], w2.x, v0); v1 = fmaf(pva[mf][2], w2.y, v1);
                            v2 = fmaf(pvb[mf][2], w2.x, v2); v3 = fmaf(pvb[mf][2], w2.y, v3);
                        }
                        v0 = fmaxf(v0, 0.f); v1 = fmaxf(v1, 0.f);
                        v2 = fmaxf(v2, 0.f); v3 = fmaxf(v3, 0.f);
                        rr[mf][2 * half]     = h2bits(__floats2half2_rn(v0, v1));
                        rr[mf][2 * half + 1] = h2bits(__floats2half2_rn(v2, v3));
                    }
                }
#pragma unroll
                for (int mf = 0; mf < 2; mf++)
                    stsm4(stm_base[mf] + np * 32, rr[mf][0], rr[mf][1], rr[mf][2], rr[mf][3]);
            }
            __syncthreads();   // A' visible before next layer's ldsm
        } else {
            // fused head: o_partial[t] = relu(v) . W3(half); direct atomics to out
            float acc3[4] = {0.f, 0.f, 0.f, 0.f};
#pragma unroll
            for (int nf = 0; nf < 8; nf++) {
                const int h = nb + nf * 8 + 2 * (lane & 3);
                const float2 bb = *(const float2*)(bias_s + 256 + h);
                const float2 w3v = *(const float2*)(w3_s + h);
#pragma unroll
                for (int mf = 0; mf < 2; mf++) {
                    float v0 = fmaxf(acc[mf][nf][0] + bb.x, 0.f);
                    float v1 = fmaxf(acc[mf][nf][1] + bb.y, 0.f);
                    float v2 = fmaxf(acc[mf][nf][2] + bb.x, 0.f);
                    float v3 = fmaxf(acc[mf][nf][3] + bb.y, 0.f);
                    acc3[0 + 2 * mf] += v0 * w3v.x + v1 * w3v.y;
                    acc3[1 + 2 * mf] += v2 * w3v.x + v3 * w3v.y;
                }
            }
#pragma unroll
            for (int s = 0; s < 4; s++) {
                acc3[s] += __shfl_xor_sync(0xffffffffu, acc3[s], 1);
                acc3[s] += __shfl_xor_sync(0xffffffffu, acc3[s], 2);
            }
            if ((lane & 3) == 0) {
                const float b3h = 0.5f * __ldg(b3g + j);   // each n-half adds b3/2
                const float* psb = ps + ((size_t)b * NJ + j) * NT;
#pragma unroll
                for (int s = 0; s < 4; s++) {
                    int t = t0 + (s >> 1) * 16 + (lane >> 2) + (s & 1) * 8;
                    float w = __ldg(psb + t);
                    atomicAdd(out + (size_t)b * NT + t,
                              (acc3[s] + b3h) * w * (1.0f / 14.0f));
                }
            }
        }
    }
}

extern "C" void kernel_launch(void* const* d_in, const int* in_sizes, int n_in,
                              void* d_out, int out_size) {
    (void)in_sizes; (void)n_in;
    const float* p  = (const float*)d_in[0];
    // d_in[1] = z (unused by the reference)
    const float* c  = (const float*)d_in[2];
    const float* ps = (const float*)d_in[3];
    const float* W0 = (const float*)d_in[4];
    const float* b0 = (const float*)d_in[5];
    const float* W1 = (const float*)d_in[6];
    const float* b1 = (const float*)d_in[7];
    const float* W2 = (const float*)d_in[8];
    const float* b2 = (const float*)d_in[9];
    const float* W3 = (const float*)d_in[10];
    const float* b3 = (const float*)d_in[11];
    float* out = (float*)d_out;

    cudaMemsetAsync(out, 0, (size_t)out_size * sizeof(float));

    convert_all<<<554, 256>>>(W0, W1, W2, c);

    cudaFuncSetAttribute(ptf_hmma, cudaFuncAttributeMaxDynamicSharedMemorySize,
                         SMEM_BYTES);
    dim3 grid(NT / 32, NB, NJ);   // 1024 x 2 x 14 = 28672 CTAs, j slowest
    ptf_hmma<<<grid, 64, SMEM_BYTES>>>(p, ps, b0, b1, b2, W0, W3, b3, out);
}